// round 11
// baseline (speedup 1.0000x reference)
#include <cuda_runtime.h>
#include <cuda_fp16.h>
#include <cstdint>

// ---------------------------------------------------------------------------
// v10: two-kernel pipeline.
// Phase 1 (xg_kernel): XG0(b,t) = b0 + Wih0 @ x(t)  for ALL (B,T), packed
//   fp16 per-consumer-thread (uint4 = 4 gates x 2 batch) into __device__
//   scratch. Pure throughput GEMM, no recurrence. 1024 CTAs x 256 thr.
// Phase 2 (lstm2): R4 lockstep skeleton; L0 warps drop Wih0 entirely
//   (acc initialized by unpacking the prefetched uint4), keeping only the
//   4-deep Whh0 chain + cell. L1 unchanged (ih1 + hh1, split accumulators).
//   No x pipeline in the loop at all.
// ---------------------------------------------------------------------------

namespace {

constexpr int T_ = 512, I_ = 128, H_ = 64, E_ = 128, C_ = 100;
constexpr int BT = 8, NCTA = 128;

constexpr int SWI = 136;
constexpr int SWH = 72;
constexpr int SXS = 136;
constexpr int SHS = 72;
constexpr int XROW = BT * SXS;      // halves per x slot
constexpr int HROW = BT * SHS;      // halves per h slot

// phase-1 smem
constexpr int P1_W = 0;             // 69632
constexpr int P1_B = 69632;         // 1024
constexpr int P1_X = 70656;         // 2 * 2176
constexpr int SMEM1 = 75008;

// phase-2 smem
constexpr int P2_WHH0 = 0;          // 36864
constexpr int P2_WIH1 = 36864;
constexpr int P2_WHH1 = 73728;
constexpr int P2_B1   = 110592;     // 1024
constexpr int P2_H0   = 111616;     // 2 * 1152
constexpr int P2_H1   = 113920;
constexpr int P2_HF   = 116224;
constexpr int P2_E    = 118272;
constexpr int P2_F    = 122368;
constexpr int SMEM2   = 126464;

#define BARRIER() asm volatile("bar.sync 0;" ::: "memory")

__device__ __forceinline__ float tanh_ap(float x) {
    float y;
    asm("tanh.approx.f32 %0, %1;" : "=f"(y) : "f"(x));
    return y;
}
__device__ __forceinline__ float fsig(float x) {
    return fmaf(0.5f, tanh_ap(0.5f * x), 0.5f);
}

__device__ __forceinline__ void mma4(float c[4], const uint32_t a[4],
                                     uint32_t b0, uint32_t b1) {
    asm volatile(
        "mma.sync.aligned.m16n8k16.row.col.f32.f16.f16.f32 "
        "{%0,%1,%2,%3},{%4,%5,%6,%7},{%8,%9},{%0,%1,%2,%3};\n"
        : "+f"(c[0]), "+f"(c[1]), "+f"(c[2]), "+f"(c[3])
        : "r"(a[0]), "r"(a[1]), "r"(a[2]), "r"(a[3]), "r"(b0), "r"(b1));
}

template <int KT, int S>
__device__ __forceinline__ void load_w(const half* __restrict__ sW, int wc, int g,
                                       int t, uint32_t f[KT][2][4]) {
#pragma unroll
    for (int kt = 0; kt < KT; kt++)
#pragma unroll
        for (int u = 0; u < 2; u++) {
            const half* p = sW + (wc * 32 + u * 16 + g) * S + kt * 16 + 2 * t;
            f[kt][u][0] = *(const uint32_t*)(p);
            f[kt][u][1] = *(const uint32_t*)(p + 8 * S);
            f[kt][u][2] = *(const uint32_t*)(p + 8);
            f[kt][u][3] = *(const uint32_t*)(p + 8 * S + 8);
        }
}

__device__ __forceinline__ void acc_set(float a[2][4], const float b[2][2]) {
#pragma unroll
    for (int u = 0; u < 2; u++) {
        a[u][0] = b[u][0]; a[u][1] = b[u][0];
        a[u][2] = b[u][1]; a[u][3] = b[u][1];
    }
}

// acc[2][4] (fp32) -> packed uint4 fp16; inverse = unpack_acc
__device__ __forceinline__ uint4 pack_acc(const float a[2][4]) {
    half2 h0 = __floats2half2_rn(a[0][0], a[0][1]);
    half2 h1 = __floats2half2_rn(a[0][2], a[0][3]);
    half2 h2 = __floats2half2_rn(a[1][0], a[1][1]);
    half2 h3 = __floats2half2_rn(a[1][2], a[1][3]);
    uint4 v;
    v.x = *(uint32_t*)&h0; v.y = *(uint32_t*)&h1;
    v.z = *(uint32_t*)&h2; v.w = *(uint32_t*)&h3;
    return v;
}
__device__ __forceinline__ void unpack_acc(uint4 v, float a[2][4]) {
    float2 p;
    p = __half22float2(*(half2*)&v.x); a[0][0] = p.x; a[0][1] = p.y;
    p = __half22float2(*(half2*)&v.y); a[0][2] = p.x; a[0][3] = p.y;
    p = __half22float2(*(half2*)&v.z); a[1][0] = p.x; a[1][1] = p.y;
    p = __half22float2(*(half2*)&v.w); a[1][2] = p.x; a[1][3] = p.y;
}

// scratch: xg[t][cta][tid256] as uint4  (512 * 128 * 256 * 16B = 268 MB)
__device__ uint4 g_xg[(size_t)T_ * NCTA * 256];

// =========================== phase 1 ===========================
__global__ void __launch_bounds__(256, 1)
xg_kernel(const float* __restrict__ x, const float* __restrict__ Wih0,
          const float* __restrict__ bih0, const float* __restrict__ bhh0)
{
    extern __shared__ unsigned char smem[];
    half*  sW = (half*)(smem + P1_W);
    float* sB = (float*)(smem + P1_B);
    half*  sX = (half*)(smem + P1_X);

    const int tid  = threadIdx.x;
    const int lane = tid & 31;
    const int wc   = tid >> 5;
    const int g    = lane >> 2;
    const int t    = lane & 3;

    for (int i = tid; i < 256 * 128; i += 256) {
        int p = i >> 7, k = i & 127;
        int m = (((p >> 4) & 1) * 2 + ((p >> 3) & 1)) * 64 + (p >> 5) * 8 + (p & 7);
        sW[p * SWI + k] = __float2half(Wih0[m * 128 + k]);
    }
    for (int i = tid; i < 256; i += 256)
        sB[i] = bih0[i] + bhh0[i];
    __syncthreads();

    uint32_t fih0[8][2][4];
    load_w<8, SWI>(sW, wc, g, t, fih0);
    float bb0[2][2];
#pragma unroll
    for (int u = 0; u < 2; u++)
#pragma unroll
        for (int v = 0; v < 2; v++)
            bb0[u][v] = sB[(2 * u + v) * 64 + wc * 8 + g];

    const int cta_b = blockIdx.x & 127;
    const int tbase = (blockIdx.x >> 7) << 6;     // 8 chunks of 64 steps
    const int b0r   = cta_b * BT;

    const int xr = tid >> 5, xi = lane * 4;
    const float* xrow = x + ((size_t)(b0r + xr) * T_) * I_ + xi;

    {   // x(tbase) -> buf0
        float4 xv = *(const float4*)(xrow + (size_t)tbase * I_);
        *(half2*)(sX + xr * SXS + xi)     = __floats2half2_rn(xv.x, xv.y);
        *(half2*)(sX + xr * SXS + xi + 2) = __floats2half2_rn(xv.z, xv.w);
    }
    float4 xpre = *(const float4*)(xrow + (size_t)(tbase + 1 < T_ ? tbase + 1 : T_ - 1) * I_);
    __syncthreads();

    for (int tt = 0; tt < 64; tt++) {
        const int p = tt & 1;
        float acc[2][4];
        acc_set(acc, bb0);
        const half* X = sX + p * XROW;
#pragma unroll
        for (int kt = 0; kt < 8; kt++) {
            const half* q = X + g * SXS + kt * 16 + 2 * t;
            uint32_t b0 = *(const uint32_t*)(q);
            uint32_t b1 = *(const uint32_t*)(q + 8);
            mma4(acc[0], fih0[kt][0], b0, b1);
            mma4(acc[1], fih0[kt][1], b0, b1);
        }
        {   // stage x(tbase+tt+1) -> buf 1-p, fetch x(tbase+tt+2)
            half* xw = sX + (1 - p) * XROW;
            *(half2*)(xw + xr * SXS + xi)     = __floats2half2_rn(xpre.x, xpre.y);
            *(half2*)(xw + xr * SXS + xi + 2) = __floats2half2_rn(xpre.z, xpre.w);
            int tn = tbase + tt + 2; if (tn > T_ - 1) tn = T_ - 1;
            xpre = *(const float4*)(xrow + (size_t)tn * I_);
        }
        g_xg[((size_t)(tbase + tt) * NCTA + cta_b) * 256 + tid] = pack_acc(acc);
        __syncthreads();
    }
}

// =========================== phase 2 ===========================
__global__ void __launch_bounds__(512, 1)
lstm2(const float* __restrict__ Whh0,
      const float* __restrict__ Wih1, const float* __restrict__ Whh1,
      const float* __restrict__ bih1, const float* __restrict__ bhh1,
      const float* __restrict__ Wproj, const float* __restrict__ bproj,
      const float* __restrict__ Wfc1, const float* __restrict__ bfc1,
      const float* __restrict__ Wfc2, const float* __restrict__ bfc2,
      float* __restrict__ out)
{
    extern __shared__ unsigned char smem[];
    half*  sWhh0 = (half*)(smem + P2_WHH0);
    half*  sWih1 = (half*)(smem + P2_WIH1);
    half*  sWhh1 = (half*)(smem + P2_WHH1);
    float* sB1   = (float*)(smem + P2_B1);
    half*  sH0   = (half*)(smem + P2_H0);
    half*  sH1   = (half*)(smem + P2_H1);
    float* sHF   = (float*)(smem + P2_HF);
    float* sE    = (float*)(smem + P2_E);
    float* sF    = (float*)(smem + P2_F);

    const int tid  = threadIdx.x;
    const int lane = tid & 31;
    const int w    = tid >> 5;
    const int wc   = w & 7;
    const int g    = lane >> 2;
    const int t    = lane & 3;
    const int cta  = blockIdx.x;
    const int b0r  = cta * BT;

    for (int i = tid; i < 256 * 64; i += 512) {
        int p = i >> 6, k = i & 63;
        int m = (((p >> 4) & 1) * 2 + ((p >> 3) & 1)) * 64 + (p >> 5) * 8 + (p & 7);
        sWhh0[p * SWH + k] = __float2half(Whh0[m * 64 + k]);
        sWih1[p * SWH + k] = __float2half(Wih1[m * 64 + k]);
        sWhh1[p * SWH + k] = __float2half(Whh1[m * 64 + k]);
    }
    for (int i = tid; i < 256; i += 512)
        sB1[i] = bih1[i] + bhh1[i];
    for (int i = tid; i < 2 * HROW; i += 512)
        sH1[i] = __float2half(0.f);
    __syncthreads();

    const int n0 = 2 * t;
    const int j  = wc * 8 + g;

    if (w < 8) {
        // ===== layer-0 warps: unpack xg + 4-deep hh chain + cell =====
        uint32_t fhh0[4][2][4];
        load_w<4, SWH>(sWhh0, wc, g, t, fhh0);
        float c00, c01;

        {   // prologue: h0(0) = cell(xg(0)), c_prev = 0
            uint4 v = g_xg[(size_t)cta * 256 + tid];
            float a[2][4];
            unpack_acc(v, a);
            float i0 = fsig(a[0][0]), i1 = fsig(a[0][1]);
            float g0 = tanh_ap(a[1][0]), g1 = tanh_ap(a[1][1]);
            float o0 = fsig(a[1][2]), o1 = fsig(a[1][3]);
            c00 = i0 * g0; c01 = i1 * g1;
            sH0[n0 * SHS + j]       = __float2half(o0 * tanh_ap(c00));
            sH0[(n0 + 1) * SHS + j] = __float2half(o1 * tanh_ap(c01));
        }
        uint4 xgCur = g_xg[((size_t)1 * NCTA + cta) * 256 + tid];
        uint4 xgN1  = g_xg[((size_t)2 * NCTA + cta) * 256 + tid];
        uint4 xgN2  = g_xg[((size_t)3 * NCTA + cta) * 256 + tid];
        BARRIER();

        for (int k = 0; k < T_; k++) {
            const int p = k & 1;
            float acc[2][4];
            unpack_acc(xgCur, acc);                 // xg(k+1) incl. bias
            const half* H0r = sH0 + p * HROW;
#pragma unroll
            for (int kt = 0; kt < 4; kt++) {
                const half* q = H0r + g * SHS + kt * 16 + 2 * t;
                uint32_t b0 = *(const uint32_t*)(q);
                uint32_t b1 = *(const uint32_t*)(q + 8);
                mma4(acc[0], fhh0[kt][0], b0, b1);
                mma4(acc[1], fhh0[kt][1], b0, b1);
            }
            {   // cell -> h0(k+1)  (phantom at k = T_-1, harmless)
                float i0 = fsig(acc[0][0]), i1 = fsig(acc[0][1]);
                float f0 = fsig(acc[0][2]), f1 = fsig(acc[0][3]);
                float g0 = tanh_ap(acc[1][0]), g1 = tanh_ap(acc[1][1]);
                float o0 = fsig(acc[1][2]), o1 = fsig(acc[1][3]);
                c00 = f0 * c00 + i0 * g0;
                c01 = f1 * c01 + i1 * g1;
                half* h0w = sH0 + (1 - p) * HROW;
                h0w[n0 * SHS + j]       = __float2half(o0 * tanh_ap(c00));
                h0w[(n0 + 1) * SHS + j] = __float2half(o1 * tanh_ap(c01));
            }
            xgCur = xgN1; xgN1 = xgN2;
            int tn = k + 4; if (tn > T_ - 1) tn = T_ - 1;
            xgN2 = g_xg[((size_t)tn * NCTA + cta) * 256 + tid];
            BARRIER();
        }
    } else {
        // ===== layer-1 warps: ih1(h0(k)) + hh1(h1(k-1)) + cell =====
        uint32_t fih1[4][2][4], fhh1[4][2][4];
        load_w<4, SWH>(sWih1, wc, g, t, fih1);
        load_w<4, SWH>(sWhh1, wc, g, t, fhh1);
        float bb1[2][2];
#pragma unroll
        for (int u = 0; u < 2; u++)
#pragma unroll
            for (int v = 0; v < 2; v++)
                bb1[u][v] = sB1[(2 * u + v) * 64 + wc * 8 + g];
        float c10 = 0.f, c11 = 0.f;
        BARRIER();

        for (int k = 0; k < T_; k++) {
            const int p = k & 1;
            float aA[2][4], aB[2][4];
            acc_set(aA, bb1);
#pragma unroll
            for (int u = 0; u < 2; u++)
#pragma unroll
                for (int e = 0; e < 4; e++) aB[u][e] = 0.f;
            const half* H0r = sH0 + p * HROW;
            const half* H1r = sH1 + p * HROW;
#pragma unroll
            for (int kt = 0; kt < 4; kt++) {
                const half* q0 = H0r + g * SHS + kt * 16 + 2 * t;
                uint32_t b0 = *(const uint32_t*)(q0);
                uint32_t b1 = *(const uint32_t*)(q0 + 8);
                mma4(aA[0], fih1[kt][0], b0, b1);
                mma4(aA[1], fih1[kt][1], b0, b1);
                const half* q1 = H1r + g * SHS + kt * 16 + 2 * t;
                uint32_t d0 = *(const uint32_t*)(q1);
                uint32_t d1 = *(const uint32_t*)(q1 + 8);
                mma4(aB[0], fhh1[kt][0], d0, d1);
                mma4(aB[1], fhh1[kt][1], d0, d1);
            }
            float a0[4], a1[4];
#pragma unroll
            for (int e = 0; e < 4; e++) {
                a0[e] = aA[0][e] + aB[0][e];
                a1[e] = aA[1][e] + aB[1][e];
            }
            float i0 = fsig(a0[0]), i1 = fsig(a0[1]);
            float f0 = fsig(a0[2]), f1 = fsig(a0[3]);
            float g0 = tanh_ap(a1[0]), g1 = tanh_ap(a1[1]);
            float o0 = fsig(a1[2]), o1 = fsig(a1[3]);
            c10 = f0 * c10 + i0 * g0;
            c11 = f1 * c11 + i1 * g1;
            float h0v = o0 * tanh_ap(c10), h1v = o1 * tanh_ap(c11);
            half* h1w = sH1 + (1 - p) * HROW;
            h1w[n0 * SHS + j]       = __float2half(h0v);
            h1w[(n0 + 1) * SHS + j] = __float2half(h1v);
            if (k == T_ - 1) {
                sHF[n0 * H_ + j]       = h0v;
                sHF[(n0 + 1) * H_ + j] = h1v;
            }
            BARRIER();
        }
    }

    __syncthreads();    // join before head

    // ---- head: proj -> relu -> fc1 -> relu -> fc2 ----
#pragma unroll
    for (int q = 0; q < 2; q++) {
        int idx = tid + q * 512;
        int r = idx >> 7, e = idx & 127;
        float a = bproj[e];
        const float* wp = Wproj + e * H_;
        const float* hp = sHF + r * H_;
#pragma unroll 8
        for (int kk = 0; kk < H_; kk++) a += hp[kk] * wp[kk];
        sE[r * E_ + e] = fmaxf(a, 0.f);
    }
    __syncthreads();
#pragma unroll
    for (int q = 0; q < 2; q++) {
        int idx = tid + q * 512;
        int r = idx >> 7, e = idx & 127;
        float a = bfc1[e];
        const float* wp = Wfc1 + e * E_;
        const float* hp = sE + r * E_;
#pragma unroll 8
        for (int kk = 0; kk < E_; kk++) a += hp[kk] * wp[kk];
        sF[r * E_ + e] = fmaxf(a, 0.f);
    }
    __syncthreads();
    for (int idx = tid; idx < BT * C_; idx += 512) {
        int r = idx / C_, c = idx - r * C_;
        float a = bfc2[c];
        const float* wp = Wfc2 + c * E_;
        const float* hp = sF + r * E_;
#pragma unroll 8
        for (int kk = 0; kk < E_; kk++) a += hp[kk] * wp[kk];
        out[(size_t)(b0r + r) * C_ + c] = a;
    }
}

}  // namespace

extern "C" void kernel_launch(void* const* d_in, const int* in_sizes, int n_in,
                              void* d_out, int out_size) {
    cudaFuncSetAttribute(xg_kernel, cudaFuncAttributeMaxDynamicSharedMemorySize,
                         SMEM1);
    cudaFuncSetAttribute(lstm2, cudaFuncAttributeMaxDynamicSharedMemorySize,
                         SMEM2);
    xg_kernel<<<1024, 256, SMEM1>>>(
        (const float*)d_in[0], (const float*)d_in[1],
        (const float*)d_in[3], (const float*)d_in[4]);
    lstm2<<<NCTA, 512, SMEM2>>>(
        (const float*)d_in[2],
        (const float*)d_in[5],  (const float*)d_in[6],
        (const float*)d_in[7],  (const float*)d_in[8],
        (const float*)d_in[9],  (const float*)d_in[10],
        (const float*)d_in[11], (const float*)d_in[12],
        (const float*)d_in[13], (const float*)d_in[14],
        (float*)d_out);
}

// round 12
// speedup vs baseline: 1.2815x; 1.2815x over previous
#include <cuda_runtime.h>
#include <cuda_fp16.h>
#include <cstdint>

// ---------------------------------------------------------------------------
// v11 = R4 (447us, best) with two exact micro-optimizations:
//  (1) L1's x-pipeline STS hoisted to the top of the step (post-barrier),
//      so the stores drain during the mma phase, not at the bar.sync
//      (BAR drain cost scales with in-flight STS). LDG also starts earlier.
//  (2) sigma-gate folding: weight rows & biases of gates i,f,o pre-scaled by
//      0.5 (exact). fsig = fma(0.5, tanh.approx(a'), 0.5) -- removes the
//      per-activation FMUL from the serial cell path.
// Everything else (sync topology, loop bodies, staging, head) == R4.
// ---------------------------------------------------------------------------

namespace {

constexpr int T_ = 512, I_ = 128, H_ = 64, E_ = 128, C_ = 100;
constexpr int BT = 8, NCTA = 128, NTHR = 512;

constexpr int SWI = 136;
constexpr int SWH = 72;
constexpr int SXS = 136;
constexpr int SHS = 72;

constexpr int OFF_WIH0 = 0;
constexpr int OFF_WHH0 = 69632;
constexpr int OFF_WIH1 = 106496;
constexpr int OFF_WHH1 = 143360;
constexpr int OFF_B0   = 180224;
constexpr int OFF_B1   = 181248;
constexpr int OFF_X    = 182272;   // 2 bufs * 2176B
constexpr int OFF_H0   = 186624;   // 2 bufs * 1152B
constexpr int OFF_H1   = 188928;
constexpr int OFF_HF   = 191232;
constexpr int OFF_E    = 193280;
constexpr int OFF_F    = 197376;
constexpr int SMEM_TOTAL = 201472;

#define BARRIER() asm volatile("bar.sync 0;" ::: "memory")

__device__ __forceinline__ float tanh_ap(float x) {
    float y;
    asm("tanh.approx.f32 %0, %1;" : "=f"(y) : "f"(x));
    return y;
}
// preact already scaled by 0.5 via folded weights
__device__ __forceinline__ float fsig_h(float xh) {
    return fmaf(0.5f, tanh_ap(xh), 0.5f);
}

__device__ __forceinline__ void mma4(float c[4], const uint32_t a[4],
                                     uint32_t b0, uint32_t b1) {
    asm volatile(
        "mma.sync.aligned.m16n8k16.row.col.f32.f16.f16.f32 "
        "{%0,%1,%2,%3},{%4,%5,%6,%7},{%8,%9},{%0,%1,%2,%3};\n"
        : "+f"(c[0]), "+f"(c[1]), "+f"(c[2]), "+f"(c[3])
        : "r"(a[0]), "r"(a[1]), "r"(a[2]), "r"(a[3]), "r"(b0), "r"(b1));
}

template <int KT, int S>
__device__ __forceinline__ void load_w(const half* __restrict__ sW, int wc, int g,
                                       int t, uint32_t f[KT][2][4]) {
#pragma unroll
    for (int kt = 0; kt < KT; kt++)
#pragma unroll
        for (int u = 0; u < 2; u++) {
            const half* p = sW + (wc * 32 + u * 16 + g) * S + kt * 16 + 2 * t;
            f[kt][u][0] = *(const uint32_t*)(p);
            f[kt][u][1] = *(const uint32_t*)(p + 8 * S);
            f[kt][u][2] = *(const uint32_t*)(p + 8);
            f[kt][u][3] = *(const uint32_t*)(p + 8 * S + 8);
        }
}

__device__ __forceinline__ void acc_set(float a[2][4], const float b[2][2]) {
#pragma unroll
    for (int u = 0; u < 2; u++) {
        a[u][0] = b[u][0]; a[u][1] = b[u][0];
        a[u][2] = b[u][1]; a[u][3] = b[u][1];
    }
}

// permuted row p -> gate q (0=i,1=f,2=g,3=o); i,f,o rows scaled by 0.5
__device__ __forceinline__ float gate_scale(int p) {
    int q = ((p >> 4) & 1) * 2 + ((p >> 3) & 1);
    return (q == 2) ? 1.0f : 0.5f;
}

__global__ void __launch_bounds__(NTHR, 1)
lstm_fused(const float* __restrict__ x,
           const float* __restrict__ Wih0, const float* __restrict__ Whh0,
           const float* __restrict__ bih0, const float* __restrict__ bhh0,
           const float* __restrict__ Wih1, const float* __restrict__ Whh1,
           const float* __restrict__ bih1, const float* __restrict__ bhh1,
           const float* __restrict__ Wproj, const float* __restrict__ bproj,
           const float* __restrict__ Wfc1, const float* __restrict__ bfc1,
           const float* __restrict__ Wfc2, const float* __restrict__ bfc2,
           float* __restrict__ out)
{
    extern __shared__ unsigned char smem[];
    half*  sWih0 = (half*)(smem + OFF_WIH0);
    half*  sWhh0 = (half*)(smem + OFF_WHH0);
    half*  sWih1 = (half*)(smem + OFF_WIH1);
    half*  sWhh1 = (half*)(smem + OFF_WHH1);
    float* sB0   = (float*)(smem + OFF_B0);
    float* sB1   = (float*)(smem + OFF_B1);
    half*  sX    = (half*)(smem + OFF_X);
    half*  sH0   = (half*)(smem + OFF_H0);
    half*  sH1   = (half*)(smem + OFF_H1);
    float* sHF   = (float*)(smem + OFF_HF);
    float* sE    = (float*)(smem + OFF_E);
    float* sF    = (float*)(smem + OFF_F);

    const int tid  = threadIdx.x;
    const int lane = tid & 31;
    const int w    = tid >> 5;
    const int wc   = w & 7;
    const int g    = lane >> 2;
    const int t    = lane & 3;
    const int b0r  = blockIdx.x * BT;

    // ---- stage permuted fp16 weights (sigma rows x0.5) + fused biases ----
    for (int i = tid; i < 256 * 128; i += NTHR) {
        int p = i >> 7, k = i & 127;
        int m = (((p >> 4) & 1) * 2 + ((p >> 3) & 1)) * 64 + (p >> 5) * 8 + (p & 7);
        sWih0[p * SWI + k] = __float2half(Wih0[m * 128 + k] * gate_scale(p));
    }
    for (int i = tid; i < 256 * 64; i += NTHR) {
        int p = i >> 6, k = i & 63;
        float sc = gate_scale(p);
        int m = (((p >> 4) & 1) * 2 + ((p >> 3) & 1)) * 64 + (p >> 5) * 8 + (p & 7);
        sWhh0[p * SWH + k] = __float2half(Whh0[m * 64 + k] * sc);
        sWih1[p * SWH + k] = __float2half(Wih1[m * 64 + k] * sc);
        sWhh1[p * SWH + k] = __float2half(Whh1[m * 64 + k] * sc);
    }
    for (int i = tid; i < 256; i += NTHR) {
        float sc = ((i >> 6) == 2) ? 1.0f : 0.5f;   // gate q = i>>6 in orig order
        sB0[i] = (bih0[i] + bhh0[i]) * sc;
        sB1[i] = (bih1[i] + bhh1[i]) * sc;
    }
    for (int i = tid; i < 2 * BT * SHS; i += NTHR)
        sH1[i] = __float2half(0.f);

    // ---- x prefetch owned by L1 warps: warp = batch row, lane = 4 floats ----
    const int xr = wc, xi = lane * 4;
    const float* xrow = x + ((size_t)(b0r + xr) * T_) * I_ + xi;
    float4 xpre = make_float4(0.f, 0.f, 0.f, 0.f);
    if (w >= 8) {
        float4 xv = *(const float4*)(xrow);            // x(0) -> buf1
        half* xw = sX + BT * SXS;
        *(half2*)(xw + xr * SXS + xi)     = __floats2half2_rn(xv.x, xv.y);
        *(half2*)(xw + xr * SXS + xi + 2) = __floats2half2_rn(xv.z, xv.w);
        xpre = *(const float4*)(xrow + I_);            // x(1)
    }
    __syncthreads();

    const int n0 = 2 * t;
    const int j  = wc * 8 + g;

    if (w < 8) {
        // ================= layer-0 warps =================
        uint32_t fih0[8][2][4], fhh0[4][2][4];
        load_w<8, SWI>(sWih0, wc, g, t, fih0);
        load_w<4, SWH>(sWhh0, wc, g, t, fhh0);
        float bb0[2][2];
#pragma unroll
        for (int u = 0; u < 2; u++)
#pragma unroll
            for (int v = 0; v < 2; v++)
                bb0[u][v] = sB0[(2 * u + v) * 64 + wc * 8 + g];

        float c00 = 0.f, c01 = 0.f;

        {   // prologue: t=0 cell (no recurrent term)
            float a[2][4];
            acc_set(a, bb0);
            const half* X = sX + BT * SXS;
#pragma unroll
            for (int kt = 0; kt < 8; kt++) {
                const half* p = X + g * SXS + kt * 16 + 2 * t;
                uint32_t b0 = *(const uint32_t*)(p);
                uint32_t b1 = *(const uint32_t*)(p + 8);
                mma4(a[0], fih0[kt][0], b0, b1);
                mma4(a[1], fih0[kt][1], b0, b1);
            }
            float i0 = fsig_h(a[0][0]), i1 = fsig_h(a[0][1]);
            float g0 = tanh_ap(a[1][0]), g1 = tanh_ap(a[1][1]);
            float o0 = fsig_h(a[1][2]), o1 = fsig_h(a[1][3]);
            c00 = i0 * g0; c01 = i1 * g1;
            sH0[n0 * SHS + j]       = __float2half(o0 * tanh_ap(c00));
            sH0[(n0 + 1) * SHS + j] = __float2half(o1 * tanh_ap(c01));
        }
        BARRIER();

        for (int k = 0; k < T_; k++) {
            const int p = k & 1;
            float a[2][4];
            acc_set(a, bb0);
            const half* H0 = sH0 + p * (BT * SHS);
#pragma unroll
            for (int kt = 0; kt < 4; kt++) {
                const half* q = H0 + g * SHS + kt * 16 + 2 * t;
                uint32_t b0 = *(const uint32_t*)(q);
                uint32_t b1 = *(const uint32_t*)(q + 8);
                mma4(a[0], fhh0[kt][0], b0, b1);
                mma4(a[1], fhh0[kt][1], b0, b1);
            }
            const half* X = sX + p * (BT * SXS);
#pragma unroll
            for (int kt = 0; kt < 8; kt++) {
                const half* q = X + g * SXS + kt * 16 + 2 * t;
                uint32_t b0 = *(const uint32_t*)(q);
                uint32_t b1 = *(const uint32_t*)(q + 8);
                mma4(a[0], fih0[kt][0], b0, b1);
                mma4(a[1], fih0[kt][1], b0, b1);
            }
            // L0 cell for t = k+1 (phantom at k = T_-1, harmless)
            float i0 = fsig_h(a[0][0]), i1 = fsig_h(a[0][1]);
            float f0 = fsig_h(a[0][2]), f1 = fsig_h(a[0][3]);
            float g0 = tanh_ap(a[1][0]), g1 = tanh_ap(a[1][1]);
            float o0 = fsig_h(a[1][2]), o1 = fsig_h(a[1][3]);
            c00 = f0 * c00 + i0 * g0;
            c01 = f1 * c01 + i1 * g1;
            half* h0w = sH0 + (1 - p) * (BT * SHS);
            h0w[n0 * SHS + j]       = __float2half(o0 * tanh_ap(c00));
            h0w[(n0 + 1) * SHS + j] = __float2half(o1 * tanh_ap(c01));
            BARRIER();
        }
    } else {
        // ================= layer-1 warps =================
        uint32_t fih1[4][2][4], fhh1[4][2][4];
        load_w<4, SWH>(sWih1, wc, g, t, fih1);
        load_w<4, SWH>(sWhh1, wc, g, t, fhh1);
        float bb1[2][2];
#pragma unroll
        for (int u = 0; u < 2; u++)
#pragma unroll
            for (int v = 0; v < 2; v++)
                bb1[u][v] = sB1[(2 * u + v) * 64 + wc * 8 + g];

        float c10 = 0.f, c11 = 0.f;

        {   // commit x(1) -> buf0, fetch x(2)
            half* xw = sX;
            *(half2*)(xw + xr * SXS + xi)     = __floats2half2_rn(xpre.x, xpre.y);
            *(half2*)(xw + xr * SXS + xi + 2) = __floats2half2_rn(xpre.z, xpre.w);
            xpre = *(const float4*)(xrow + 2 * (size_t)I_);
        }
        BARRIER();

        for (int k = 0; k < T_; k++) {
            const int p = k & 1;
            {   // x pipeline FIRST (post-barrier): STS x(k+2) -> buf 1-p so the
                // stores drain during the mma phase; LDG x(k+3) starts early.
                half* xw = sX + (1 - p) * (BT * SXS);
                *(half2*)(xw + xr * SXS + xi)     = __floats2half2_rn(xpre.x, xpre.y);
                *(half2*)(xw + xr * SXS + xi + 2) = __floats2half2_rn(xpre.z, xpre.w);
                int tn = k + 3; if (tn > T_ - 1) tn = T_ - 1;
                xpre = *(const float4*)(xrow + (size_t)tn * I_);
            }
            float a[2][4];
            acc_set(a, bb1);
            const half* H0 = sH0 + p * (BT * SHS);
            const half* H1 = sH1 + p * (BT * SHS);
#pragma unroll
            for (int kt = 0; kt < 4; kt++) {
                const half* q0 = H0 + g * SHS + kt * 16 + 2 * t;
                uint32_t b0 = *(const uint32_t*)(q0);
                uint32_t b1 = *(const uint32_t*)(q0 + 8);
                mma4(a[0], fih1[kt][0], b0, b1);
                mma4(a[1], fih1[kt][1], b0, b1);
                const half* q1 = H1 + g * SHS + kt * 16 + 2 * t;
                uint32_t d0 = *(const uint32_t*)(q1);
                uint32_t d1 = *(const uint32_t*)(q1 + 8);
                mma4(a[0], fhh1[kt][0], d0, d1);
                mma4(a[1], fhh1[kt][1], d0, d1);
            }
            // L1 cell for t = k
            float i0 = fsig_h(a[0][0]), i1 = fsig_h(a[0][1]);
            float f0 = fsig_h(a[0][2]), f1 = fsig_h(a[0][3]);
            float g0 = tanh_ap(a[1][0]), g1 = tanh_ap(a[1][1]);
            float o0 = fsig_h(a[1][2]), o1 = fsig_h(a[1][3]);
            c10 = f0 * c10 + i0 * g0;
            c11 = f1 * c11 + i1 * g1;
            float h0v = o0 * tanh_ap(c10), h1v = o1 * tanh_ap(c11);
            half* h1w = sH1 + (1 - p) * (BT * SHS);
            h1w[n0 * SHS + j]       = __float2half(h0v);
            h1w[(n0 + 1) * SHS + j] = __float2half(h1v);
            if (k == T_ - 1) {
                sHF[n0 * H_ + j]       = h0v;
                sHF[(n0 + 1) * H_ + j] = h1v;
            }
            BARRIER();
        }
    }

    __syncthreads();

    // ---- head: proj -> relu -> fc1 -> relu -> fc2 ----
#pragma unroll
    for (int q = 0; q < 2; q++) {
        int idx = tid + q * NTHR;
        int r = idx >> 7, e = idx & 127;
        float a = bproj[e];
        const float* wp = Wproj + e * H_;
        const float* hp = sHF + r * H_;
#pragma unroll 8
        for (int kk = 0; kk < H_; kk++) a += hp[kk] * wp[kk];
        sE[r * E_ + e] = fmaxf(a, 0.f);
    }
    __syncthreads();
#pragma unroll
    for (int q = 0; q < 2; q++) {
        int idx = tid + q * NTHR;
        int r = idx >> 7, e = idx & 127;
        float a = bfc1[e];
        const float* wp = Wfc1 + e * E_;
        const float* hp = sE + r * E_;
#pragma unroll 8
        for (int kk = 0; kk < E_; kk++) a += hp[kk] * wp[kk];
        sF[r * E_ + e] = fmaxf(a, 0.f);
    }
    __syncthreads();
    for (int idx = tid; idx < BT * C_; idx += NTHR) {
        int r = idx / C_, c = idx - r * C_;
        float a = bfc2[c];
        const float* wp = Wfc2 + c * E_;
        const float* hp = sF + r * E_;
#pragma unroll 8
        for (int kk = 0; kk < E_; kk++) a += hp[kk] * wp[kk];
        out[(size_t)(b0r + r) * C_ + c] = a;
    }
}

}  // namespace

extern "C" void kernel_launch(void* const* d_in, const int* in_sizes, int n_in,
                              void* d_out, int out_size) {
    cudaFuncSetAttribute(lstm_fused, cudaFuncAttributeMaxDynamicSharedMemorySize,
                         SMEM_TOTAL);
    lstm_fused<<<NCTA, NTHR, SMEM_TOTAL>>>(
        (const float*)d_in[0],
        (const float*)d_in[1],  (const float*)d_in[2],
        (const float*)d_in[3],  (const float*)d_in[4],
        (const float*)d_in[5],  (const float*)d_in[6],
        (const float*)d_in[7],  (const float*)d_in[8],
        (const float*)d_in[9],  (const float*)d_in[10],
        (const float*)d_in[11], (const float*)d_in[12],
        (const float*)d_in[13], (const float*)d_in[14],
        (float*)d_out);
}